// round 1
// baseline (speedup 1.0000x reference)
#include <cuda_runtime.h>

#define DF   64
#define NN   100000
#define EE   1600000
#define EPSV 1e-5f

// ---------------- scratch (device globals; no allocation allowed) ----------
__device__ float g_deg[NN];
__device__ float g_dinv[NN];
__device__ int   g_cnt[NN];
__device__ int   g_fill[NN];
__device__ int   g_rowptr[NN];
__device__ int   g_csrc[EE];
__device__ float g_cnrm[EE];
__device__ float g_h1[(size_t)NN * DF];
__device__ float g_ha[(size_t)NN * DF];
__device__ float g_h2[(size_t)NN * DF];
__device__ float g_bnsum[DF];
__device__ float g_bnsq[DF];
__device__ float g_bna[DF];
__device__ float g_bnc[DF];
__device__ int   g_part[256];

// ---------------- init: deg=1 (self loop), counters/stats = 0 --------------
__global__ void k_init(int n) {
    int i = blockIdx.x * blockDim.x + threadIdx.x;
    if (i < n) { g_deg[i] = 1.0f; g_cnt[i] = 0; g_fill[i] = 0; }
    if (i < DF) { g_bnsum[i] = 0.0f; g_bnsq[i] = 0.0f; }
}

// ---------------- edge pass 1: weighted in-degree + per-dst edge count -----
__global__ void k_edge_deg(const int* __restrict__ ei,
                           const float* __restrict__ w, int E) {
    int e = blockIdx.x * blockDim.x + threadIdx.x;
    if (e < E) {
        int d = ei[E + e];
        atomicAdd(&g_deg[d], w[e]);
        atomicAdd(&g_cnt[d], 1);
    }
}

__global__ void k_dinv(int n) {
    int i = blockIdx.x * blockDim.x + threadIdx.x;
    if (i < n) {
        float d = g_deg[i];
        g_dinv[i] = (d > 0.0f) ? rsqrtf(d) : 0.0f;
    }
}

// ---------------- 3-kernel exclusive scan of g_cnt -> g_rowptr -------------
__global__ void k_scan_a(int n) {
    __shared__ int s[1024];
    int t = threadIdx.x;
    int i = blockIdx.x * 1024 + t;
    s[t] = (i < n) ? g_cnt[i] : 0;
    __syncthreads();
    for (int off = 512; off > 0; off >>= 1) {
        if (t < off) s[t] += s[t + off];
        __syncthreads();
    }
    if (t == 0) g_part[blockIdx.x] = s[0];
}

__global__ void k_scan_b(int nb) {
    if (threadIdx.x == 0) {
        int acc = 0;
        for (int b = 0; b < nb; b++) { int v = g_part[b]; g_part[b] = acc; acc += v; }
    }
}

__global__ void k_scan_c(int n) {
    __shared__ int s[1024];
    int t = threadIdx.x;
    int i = blockIdx.x * 1024 + t;
    int v = (i < n) ? g_cnt[i] : 0;
    s[t] = v;
    __syncthreads();
    for (int off = 1; off < 1024; off <<= 1) {
        int add = (t >= off) ? s[t - off] : 0;
        __syncthreads();
        s[t] += add;
        __syncthreads();
    }
    if (i < n) g_rowptr[i] = g_part[blockIdx.x] + s[t] - v;  // exclusive
}

// ---------------- edge pass 2: fill CSR (src idx + precomputed norm) -------
__global__ void k_fill(const int* __restrict__ ei,
                       const float* __restrict__ w, int E) {
    int e = blockIdx.x * blockDim.x + threadIdx.x;
    if (e < E) {
        int s = ei[e];
        int d = ei[E + e];
        float wf = w[e];
        int slot = g_rowptr[d] + atomicAdd(&g_fill[d], 1);
        g_csrc[slot] = s;
        g_cnrm[slot] = g_dinv[s] * wf * g_dinv[d];
    }
}

// ---------------- GEMM: Y[N,64] = f(X)[N,64] @ W[64,64] --------------------
// 256 threads, 128-row tile. Thread = (rg 0..31, cg 0..7); 8 rows x 8 cols.
// BN=true applies y = relu(a[k]*x + c[k]) to input elements (fused BN+ReLU).
template <bool BN>
__global__ void __launch_bounds__(256) k_gemm(const float* __restrict__ X,
                                              const float* __restrict__ W,
                                              float* __restrict__ Y, int n) {
    __shared__ __align__(16) float sW[64][64];
    __shared__ __align__(16) float sA[64];
    __shared__ __align__(16) float sC[64];
    int tid = threadIdx.x;

    {   // load W (4096 floats) cooperatively
        const float4* W4 = (const float4*)W;
        float4* sW4 = (float4*)&sW[0][0];
        #pragma unroll
        for (int i = 0; i < 4; i++) sW4[tid + 256 * i] = W4[tid + 256 * i];
    }
    if (BN && tid < 64) { sA[tid] = g_bna[tid]; sC[tid] = g_bnc[tid]; }
    __syncthreads();

    int rg = tid >> 3;          // 0..31
    int cg = tid & 7;           // 0..7
    int rbase = blockIdx.x * 128 + rg;   // rows rbase + 32*rr

    float acc[8][8];
    #pragma unroll
    for (int a = 0; a < 8; a++)
        #pragma unroll
        for (int b = 0; b < 8; b++) acc[a][b] = 0.0f;

    const float4* X4 = (const float4*)X;

    #pragma unroll
    for (int k4 = 0; k4 < 16; k4++) {
        float4 xv[8];
        #pragma unroll
        for (int rr = 0; rr < 8; rr++) {
            int r = rbase + 32 * rr;
            xv[rr] = (r < n) ? X4[(size_t)r * 16 + k4] : make_float4(0.f, 0.f, 0.f, 0.f);
        }
        if (BN) {
            float4 a4 = ((const float4*)sA)[k4];
            float4 c4 = ((const float4*)sC)[k4];
            #pragma unroll
            for (int rr = 0; rr < 8; rr++) {
                xv[rr].x = fmaxf(fmaf(a4.x, xv[rr].x, c4.x), 0.0f);
                xv[rr].y = fmaxf(fmaf(a4.y, xv[rr].y, c4.y), 0.0f);
                xv[rr].z = fmaxf(fmaf(a4.z, xv[rr].z, c4.z), 0.0f);
                xv[rr].w = fmaxf(fmaf(a4.w, xv[rr].w, c4.w), 0.0f);
            }
        }
        #pragma unroll
        for (int kk = 0; kk < 4; kk++) {
            const float* wrow = &sW[k4 * 4 + kk][cg * 8];
            float4 w0 = *(const float4*)(wrow);
            float4 w1 = *(const float4*)(wrow + 4);
            #pragma unroll
            for (int rr = 0; rr < 8; rr++) {
                float xk = ((const float*)&xv[rr])[kk];
                acc[rr][0] = fmaf(xk, w0.x, acc[rr][0]);
                acc[rr][1] = fmaf(xk, w0.y, acc[rr][1]);
                acc[rr][2] = fmaf(xk, w0.z, acc[rr][2]);
                acc[rr][3] = fmaf(xk, w0.w, acc[rr][3]);
                acc[rr][4] = fmaf(xk, w1.x, acc[rr][4]);
                acc[rr][5] = fmaf(xk, w1.y, acc[rr][5]);
                acc[rr][6] = fmaf(xk, w1.z, acc[rr][6]);
                acc[rr][7] = fmaf(xk, w1.w, acc[rr][7]);
            }
        }
    }

    float4* Y4 = (float4*)Y;
    #pragma unroll
    for (int rr = 0; rr < 8; rr++) {
        int r = rbase + 32 * rr;
        if (r < n) {
            float4 o0 = make_float4(acc[rr][0], acc[rr][1], acc[rr][2], acc[rr][3]);
            float4 o1 = make_float4(acc[rr][4], acc[rr][5], acc[rr][6], acc[rr][7]);
            Y4[(size_t)r * 16 + cg * 2]     = o0;
            Y4[(size_t)r * 16 + cg * 2 + 1] = o1;
        }
    }
}

// ---------------- aggregation: warp per node, float2 per lane --------------
// out[i] = H[i]*dinv[i]^2 + sum_e H[csrc[e]]*cnrm[e] + bias
// STATS=true: also accumulate per-feature sum & sumsq for BN (block reduce).
template <bool STATS>
__global__ void __launch_bounds__(256) k_agg(const float* __restrict__ H,
                                             const float* __restrict__ bias,
                                             float* __restrict__ out, int n) {
    __shared__ float ssum[64];
    __shared__ float ssq[64];
    int wid  = threadIdx.x >> 5;
    int lane = threadIdx.x & 31;
    if (STATS) {
        if (threadIdx.x < 64) { ssum[threadIdx.x] = 0.0f; ssq[threadIdx.x] = 0.0f; }
        __syncthreads();
    }

    int i = blockIdx.x * 8 + wid;
    float2 acc = make_float2(0.0f, 0.0f);
    bool valid = (i < n);
    if (valid) {
        float dv = g_dinv[i];
        float sw = dv * dv;
        float2 hv = ((const float2*)(H + (size_t)i * 64))[lane];
        acc.x = hv.x * sw;
        acc.y = hv.y * sw;

        int e   = g_rowptr[i];
        int end = e + g_cnt[i];

        // 4-wide software pipeline for MLP
        for (; e + 4 <= end; e += 4) {
            int   s0 = g_csrc[e],     s1 = g_csrc[e + 1];
            int   s2 = g_csrc[e + 2], s3 = g_csrc[e + 3];
            float n0 = g_cnrm[e],     n1 = g_cnrm[e + 1];
            float n2 = g_cnrm[e + 2], n3 = g_cnrm[e + 3];
            float2 a0 = ((const float2*)(H + (size_t)s0 * 64))[lane];
            float2 a1 = ((const float2*)(H + (size_t)s1 * 64))[lane];
            float2 a2 = ((const float2*)(H + (size_t)s2 * 64))[lane];
            float2 a3 = ((const float2*)(H + (size_t)s3 * 64))[lane];
            acc.x = fmaf(n0, a0.x, acc.x); acc.y = fmaf(n0, a0.y, acc.y);
            acc.x = fmaf(n1, a1.x, acc.x); acc.y = fmaf(n1, a1.y, acc.y);
            acc.x = fmaf(n2, a2.x, acc.x); acc.y = fmaf(n2, a2.y, acc.y);
            acc.x = fmaf(n3, a3.x, acc.x); acc.y = fmaf(n3, a3.y, acc.y);
        }
        for (; e < end; e++) {
            int s = g_csrc[e];
            float nr = g_cnrm[e];
            float2 a0 = ((const float2*)(H + (size_t)s * 64))[lane];
            acc.x = fmaf(nr, a0.x, acc.x);
            acc.y = fmaf(nr, a0.y, acc.y);
        }

        float2 b = ((const float2*)bias)[lane];
        acc.x += b.x;
        acc.y += b.y;
        ((float2*)(out + (size_t)i * 64))[lane] = acc;
    }

    if (STATS) {
        if (valid) {
            atomicAdd(&ssum[2 * lane],     acc.x);
            atomicAdd(&ssum[2 * lane + 1], acc.y);
            atomicAdd(&ssq[2 * lane],      acc.x * acc.x);
            atomicAdd(&ssq[2 * lane + 1],  acc.y * acc.y);
        }
        __syncthreads();
        if (threadIdx.x < 64) {
            atomicAdd(&g_bnsum[threadIdx.x], ssum[threadIdx.x]);
            atomicAdd(&g_bnsq[threadIdx.x],  ssq[threadIdx.x]);
        }
    }
}

// ---------------- BN finalize: a = gamma*rstd, c = beta - mu*a --------------
__global__ void k_bnfin(const float* __restrict__ gamma,
                        const float* __restrict__ beta, float invn) {
    int f = threadIdx.x;
    if (f < DF) {
        float mu  = g_bnsum[f] * invn;
        float var = g_bnsq[f] * invn - mu * mu;
        float rstd = rsqrtf(var + EPSV);
        float a = gamma[f] * rstd;
        g_bna[f] = a;
        g_bnc[f] = beta[f] - mu * a;
    }
}

// ---------------------------------------------------------------------------
extern "C" void kernel_launch(void* const* d_in, const int* in_sizes, int n_in,
                              void* d_out, int out_size) {
    const float* x     = (const float*)d_in[0];
    const int*   ei    = (const int*)d_in[1];
    const float* ew    = (const float*)d_in[2];
    const float* W1    = (const float*)d_in[3];
    const float* b1    = (const float*)d_in[4];
    const float* gamma = (const float*)d_in[5];
    const float* beta  = (const float*)d_in[6];
    const float* W2    = (const float*)d_in[7];
    const float* b2    = (const float*)d_in[8];

    int N = in_sizes[0] / DF;
    int E = in_sizes[2];
    if (N > NN || E > EE) return;

    float *p_h1, *p_ha, *p_h2;
    cudaGetSymbolAddress((void**)&p_h1, g_h1);
    cudaGetSymbolAddress((void**)&p_ha, g_ha);
    cudaGetSymbolAddress((void**)&p_h2, g_h2);

    int nb = (N + 1023) / 1024;

    k_init<<<(N + 255) / 256, 256>>>(N);
    k_edge_deg<<<(E + 255) / 256, 256>>>(ei, ew, E);
    k_dinv<<<(N + 255) / 256, 256>>>(N);
    k_scan_a<<<nb, 1024>>>(N);
    k_scan_b<<<1, 32>>>(nb);
    k_scan_c<<<nb, 1024>>>(N);
    k_fill<<<(E + 255) / 256, 256>>>(ei, ew, E);

    k_gemm<false><<<(N + 127) / 128, 256>>>(x, W1, p_h1, N);
    k_agg<true><<<(N + 7) / 8, 256>>>(p_h1, b1, p_ha, N);
    k_bnfin<<<1, 64>>>(gamma, beta, 1.0f / (float)N);
    k_gemm<true><<<(N + 127) / 128, 256>>>(p_ha, W2, p_h2, N);
    k_agg<false><<<(N + 7) / 8, 256>>>(p_h2, b2, (float*)d_out, N);
}

// round 3
// speedup vs baseline: 1.1256x; 1.1256x over previous
#include <cuda_runtime.h>

#define DF   64
#define NN   100000
#define EE   1600000
#define EPSV 1e-5f

// ---------------- scratch (device globals; zero-initialized at load) -------
// Invariant: every kernel_launch call leaves g_deg/g_cnt/g_fill/g_bnsum/g_bnsq
// all-zero (tail cleanup in the final kernel), matching first-call zero-init.
// g_dinv/g_rowptr/g_edge are fully rewritten every call, no invariant needed.
__device__ float g_deg[NN];                 // weighted in-degree (excl. self loop)
__device__ float g_dinv[NN];
__device__ int   g_cnt[NN];
__device__ int   g_fill[NN];
__device__ int   g_rowptr[NN + 1];          // exclusive prefix; rowptr[N] = E
__device__ unsigned long long g_edge[EE];   // packed: (norm_bits<<32) | src
__device__ float g_h1[(size_t)NN * DF];
__device__ float g_ha[(size_t)NN * DF];
__device__ float g_h2[(size_t)NN * DF];
__device__ float g_bnsum[DF];
__device__ float g_bnsq[DF];
__device__ int   g_part[128];

// ---------------- edge pass 1: weighted in-degree + per-dst edge count -----
__global__ void k_edge_deg(const int* __restrict__ ei,
                           const float* __restrict__ w, int E) {
    int e4 = (blockIdx.x * blockDim.x + threadIdx.x) * 4;
    if (e4 + 3 < E) {
        int4   d4 = *(const int4*)&ei[E + e4];
        float4 w4 = *(const float4*)&w[e4];
        atomicAdd(&g_deg[d4.x], w4.x); atomicAdd(&g_cnt[d4.x], 1);
        atomicAdd(&g_deg[d4.y], w4.y); atomicAdd(&g_cnt[d4.y], 1);
        atomicAdd(&g_deg[d4.z], w4.z); atomicAdd(&g_cnt[d4.z], 1);
        atomicAdd(&g_deg[d4.w], w4.w); atomicAdd(&g_cnt[d4.w], 1);
    } else {
        for (int e = e4; e < E; e++) {
            int d = ei[E + e];
            atomicAdd(&g_deg[d], w[e]);
            atomicAdd(&g_cnt[d], 1);
        }
    }
}

// ---------------- scan stage A: dinv + per-block sums ----------------------
__global__ void k_scan_a(int n) {
    __shared__ int s[1024];
    int t = threadIdx.x;
    int i = blockIdx.x * 1024 + t;
    if (i < n) g_dinv[i] = rsqrtf(g_deg[i] + 1.0f);   // +1 = self loop
    s[t] = (i < n) ? g_cnt[i] : 0;
    __syncthreads();
    for (int off = 512; off > 0; off >>= 1) {
        if (t < off) s[t] += s[t + off];
        __syncthreads();
    }
    if (t == 0) g_part[blockIdx.x] = s[0];
}

// ---------------- scan stage B: inline partial-prefix + local scan ---------
__global__ void k_scan_c(int n, int nb) {
    __shared__ int s[1024];
    __shared__ int sp[128];
    int t = threadIdx.x;
    int i = blockIdx.x * 1024 + t;

    if (t < 128) sp[t] = (t < nb) ? g_part[t] : 0;
    __syncthreads();
    #pragma unroll
    for (int off = 1; off < 128; off <<= 1) {
        int a = (t < 128 && t >= off) ? sp[t - off] : 0;
        __syncthreads();
        if (t < 128) sp[t] += a;
        __syncthreads();
    }

    int v = (i < n) ? g_cnt[i] : 0;
    s[t] = v;
    __syncthreads();
    for (int off = 1; off < 1024; off <<= 1) {
        int a = (t >= off) ? s[t - off] : 0;
        __syncthreads();
        s[t] += a;
        __syncthreads();
    }
    int bp = (blockIdx.x > 0) ? sp[blockIdx.x - 1] : 0;
    if (i < n) g_rowptr[i] = bp + s[t] - v;          // exclusive prefix
    if (i == n - 1) g_rowptr[n] = bp + s[t];         // total = E
}

// ---------------- edge pass 2: fill CSR, single 8B scattered store ---------
__global__ void k_fill(const int* __restrict__ ei,
                       const float* __restrict__ w, int E) {
    int e = blockIdx.x * blockDim.x + threadIdx.x;
    if (e < E) {
        int s = ei[e];
        int d = ei[E + e];
        float nrm = g_dinv[s] * w[e] * g_dinv[d];
        int slot = g_rowptr[d] + atomicAdd(&g_fill[d], 1);
        g_edge[slot] = ((unsigned long long)__float_as_uint(nrm) << 32) |
                       (unsigned long long)(unsigned)s;
    }
}

// ---------------- GEMM: Y[N,64] = f(X)[N,64] @ W[64,64] --------------------
// BN=true: input transform y = relu(a[k]*x + c[k]); a,c computed inline from
// batch stats (redundant per block, 64 threads, trivial).
template <bool BN>
__global__ void __launch_bounds__(256) k_gemm(const float* __restrict__ X,
                                              const float* __restrict__ W,
                                              float* __restrict__ Y, int n,
                                              const float* __restrict__ gamma,
                                              const float* __restrict__ beta,
                                              float invn) {
    __shared__ __align__(16) float sW[64][64];
    __shared__ __align__(16) float sA[64];
    __shared__ __align__(16) float sC[64];
    int tid = threadIdx.x;

    {   // load W (4096 floats) cooperatively
        const float4* W4 = (const float4*)W;
        float4* sW4 = (float4*)&sW[0][0];
        #pragma unroll
        for (int i = 0; i < 4; i++) sW4[tid + 256 * i] = W4[tid + 256 * i];
    }
    if (BN && tid < 64) {
        float mu   = g_bnsum[tid] * invn;
        float var  = g_bnsq[tid] * invn - mu * mu;
        float a    = gamma[tid] * rsqrtf(var + EPSV);
        sA[tid] = a;
        sC[tid] = beta[tid] - mu * a;
    }
    __syncthreads();

    int rg = tid >> 3;                   // 0..31
    int cg = tid & 7;                    // 0..7
    int rbase = blockIdx.x * 128 + rg;   // rows rbase + 32*rr

    float acc[8][8];
    #pragma unroll
    for (int a = 0; a < 8; a++)
        #pragma unroll
        for (int b = 0; b < 8; b++) acc[a][b] = 0.0f;

    const float4* X4 = (const float4*)X;

    #pragma unroll
    for (int k4 = 0; k4 < 16; k4++) {
        float4 xv[8];
        #pragma unroll
        for (int rr = 0; rr < 8; rr++) {
            int r = rbase + 32 * rr;
            xv[rr] = (r < n) ? X4[(size_t)r * 16 + k4] : make_float4(0.f, 0.f, 0.f, 0.f);
        }
        if (BN) {
            float4 a4 = ((const float4*)sA)[k4];
            float4 c4 = ((const float4*)sC)[k4];
            #pragma unroll
            for (int rr = 0; rr < 8; rr++) {
                xv[rr].x = fmaxf(fmaf(a4.x, xv[rr].x, c4.x), 0.0f);
                xv[rr].y = fmaxf(fmaf(a4.y, xv[rr].y, c4.y), 0.0f);
                xv[rr].z = fmaxf(fmaf(a4.z, xv[rr].z, c4.z), 0.0f);
                xv[rr].w = fmaxf(fmaf(a4.w, xv[rr].w, c4.w), 0.0f);
            }
        }
        #pragma unroll
        for (int kk = 0; kk < 4; kk++) {
            const float* wrow = &sW[k4 * 4 + kk][cg * 8];
            float4 w0 = *(const float4*)(wrow);
            float4 w1 = *(const float4*)(wrow + 4);
            #pragma unroll
            for (int rr = 0; rr < 8; rr++) {
                float xk = ((const float*)&xv[rr])[kk];
                acc[rr][0] = fmaf(xk, w0.x, acc[rr][0]);
                acc[rr][1] = fmaf(xk, w0.y, acc[rr][1]);
                acc[rr][2] = fmaf(xk, w0.z, acc[rr][2]);
                acc[rr][3] = fmaf(xk, w0.w, acc[rr][3]);
                acc[rr][4] = fmaf(xk, w1.x, acc[rr][4]);
                acc[rr][5] = fmaf(xk, w1.y, acc[rr][5]);
                acc[rr][6] = fmaf(xk, w1.z, acc[rr][6]);
                acc[rr][7] = fmaf(xk, w1.w, acc[rr][7]);
            }
        }
    }

    float4* Y4 = (float4*)Y;
    #pragma unroll
    for (int rr = 0; rr < 8; rr++) {
        int r = rbase + 32 * rr;
        if (r < n) {
            Y4[(size_t)r * 16 + cg * 2] =
                make_float4(acc[rr][0], acc[rr][1], acc[rr][2], acc[rr][3]);
            Y4[(size_t)r * 16 + cg * 2 + 1] =
                make_float4(acc[rr][4], acc[rr][5], acc[rr][6], acc[rr][7]);
        }
    }
}

// ---------------- aggregation: 16 lanes per node, float4 per lane ----------
// out[i] = H[i]*dinv[i]^2 + sum_e H[src(e)]*norm(e) + bias
// Edge range comes from rowptr[i]..rowptr[i+1] ONLY (g_cnt is never read here,
// so the CLEAN tail cannot race with other blocks' reads).
// STATS: per-feature sum/sumsq via conflict-free smem transpose-reduce.
// CLEAN: tail cleanup restoring the all-zero scratch invariant.
template <bool STATS, bool CLEAN>
__global__ void __launch_bounds__(256) k_agg(const float* __restrict__ H,
                                             const float* __restrict__ bias,
                                             float* __restrict__ out, int n) {
    int tid  = threadIdx.x;
    int sub  = tid >> 4;        // 0..15 node slot
    int l4   = tid & 15;        // feature group (4 floats)
    int i    = blockIdx.x * 16 + sub;

    float4 acc = make_float4(0.f, 0.f, 0.f, 0.f);
    if (i < n) {
        float dv = g_dinv[i];
        float sw = dv * dv;
        float4 hv = ((const float4*)(H + (size_t)i * 64))[l4];
        acc.x = hv.x * sw; acc.y = hv.y * sw;
        acc.z = hv.z * sw; acc.w = hv.w * sw;

        int e   = g_rowptr[i];
        int end = g_rowptr[i + 1];

        for (; e + 4 <= end; e += 4) {
            unsigned long long p0 = g_edge[e];
            unsigned long long p1 = g_edge[e + 1];
            unsigned long long p2 = g_edge[e + 2];
            unsigned long long p3 = g_edge[e + 3];
            const float4* r0 = (const float4*)(H + (size_t)(unsigned)p0 * 64);
            const float4* r1 = (const float4*)(H + (size_t)(unsigned)p1 * 64);
            const float4* r2 = (const float4*)(H + (size_t)(unsigned)p2 * 64);
            const float4* r3 = (const float4*)(H + (size_t)(unsigned)p3 * 64);
            float4 a0 = r0[l4], a1 = r1[l4], a2 = r2[l4], a3 = r3[l4];
            float n0 = __uint_as_float((unsigned)(p0 >> 32));
            float n1 = __uint_as_float((unsigned)(p1 >> 32));
            float n2 = __uint_as_float((unsigned)(p2 >> 32));
            float n3 = __uint_as_float((unsigned)(p3 >> 32));
            acc.x = fmaf(n0, a0.x, acc.x); acc.y = fmaf(n0, a0.y, acc.y);
            acc.z = fmaf(n0, a0.z, acc.z); acc.w = fmaf(n0, a0.w, acc.w);
            acc.x = fmaf(n1, a1.x, acc.x); acc.y = fmaf(n1, a1.y, acc.y);
            acc.z = fmaf(n1, a1.z, acc.z); acc.w = fmaf(n1, a1.w, acc.w);
            acc.x = fmaf(n2, a2.x, acc.x); acc.y = fmaf(n2, a2.y, acc.y);
            acc.z = fmaf(n2, a2.z, acc.z); acc.w = fmaf(n2, a2.w, acc.w);
            acc.x = fmaf(n3, a3.x, acc.x); acc.y = fmaf(n3, a3.y, acc.y);
            acc.z = fmaf(n3, a3.z, acc.z); acc.w = fmaf(n3, a3.w, acc.w);
        }
        for (; e < end; e++) {
            unsigned long long p0 = g_edge[e];
            const float4* r0 = (const float4*)(H + (size_t)(unsigned)p0 * 64);
            float4 a0 = r0[l4];
            float n0 = __uint_as_float((unsigned)(p0 >> 32));
            acc.x = fmaf(n0, a0.x, acc.x); acc.y = fmaf(n0, a0.y, acc.y);
            acc.z = fmaf(n0, a0.z, acc.z); acc.w = fmaf(n0, a0.w, acc.w);
        }

        float4 b = ((const float4*)bias)[l4];
        float4 o = make_float4(acc.x + b.x, acc.y + b.y, acc.z + b.z, acc.w + b.w);
        ((float4*)(out + (size_t)i * 64))[l4] = o;
        acc = o;   // stats are over the biased output
    }

    if (STATS) {
        __shared__ __align__(16) float sacc[16][80];   // 80-pad: conflict-free both phases
        ((float4*)&sacc[sub][l4 * 4])[0] = acc;        // invalid i contributed zeros
        __syncthreads();
        if (tid < 64) {
            float s = 0.f, q = 0.f;
            #pragma unroll
            for (int k = 0; k < 16; k++) {
                float v = sacc[k][tid];
                s += v;
                q += v * v;
            }
            atomicAdd(&g_bnsum[tid], s);
            atomicAdd(&g_bnsq[tid],  q);
        }
    }

    if (CLEAN) {
        // restore all-zero invariant for next call (matches static zero-init).
        // Safe: this kernel reads only g_dinv/g_rowptr/g_edge/H, none of which
        // are written here.
        int g = blockIdx.x * 256 + tid;
        if (g < n) { g_deg[g] = 0.0f; g_cnt[g] = 0; g_fill[g] = 0; }
        if (g < DF) { g_bnsum[g] = 0.0f; g_bnsq[g] = 0.0f; }
    }
}

// ---------------------------------------------------------------------------
extern "C" void kernel_launch(void* const* d_in, const int* in_sizes, int n_in,
                              void* d_out, int out_size) {
    const float* x     = (const float*)d_in[0];
    const int*   ei    = (const int*)d_in[1];
    const float* ew    = (const float*)d_in[2];
    const float* W1    = (const float*)d_in[3];
    const float* b1    = (const float*)d_in[4];
    const float* gamma = (const float*)d_in[5];
    const float* beta  = (const float*)d_in[6];
    const float* W2    = (const float*)d_in[7];
    const float* b2    = (const float*)d_in[8];

    int N = in_sizes[0] / DF;
    int E = in_sizes[2];
    if (N > NN || E > EE) return;

    float *p_h1, *p_ha, *p_h2;
    cudaGetSymbolAddress((void**)&p_h1, g_h1);
    cudaGetSymbolAddress((void**)&p_ha, g_ha);
    cudaGetSymbolAddress((void**)&p_h2, g_h2);

    int nb = (N + 1023) / 1024;
    float invn = 1.0f / (float)N;

    k_edge_deg<<<(E + 1023) / 1024, 256>>>(ei, ew, E);
    k_scan_a<<<nb, 1024>>>(N);
    k_scan_c<<<nb, 1024>>>(N, nb);
    k_fill<<<(E + 255) / 256, 256>>>(ei, ew, E);

    k_gemm<false><<<(N + 127) / 128, 256>>>(x, W1, p_h1, N, nullptr, nullptr, 0.f);
    k_agg<true, false><<<(N + 15) / 16, 256>>>(p_h1, b1, p_ha, N);
    k_gemm<true><<<(N + 127) / 128, 256>>>(p_ha, W2, p_h2, N, gamma, beta, invn);
    k_agg<false, true><<<(N + 15) / 16, 256>>>(p_h2, b2, (float*)d_out, N);
}

// round 4
// speedup vs baseline: 1.2400x; 1.1017x over previous
#include <cuda_runtime.h>
#include <cuda_fp16.h>

#define DF   64
#define NN   100000
#define EE   1600000
#define EPSV 1e-5f

// ---------------- scratch (device globals; zero-initialized at load) -------
// Invariant: every call leaves g_deg/g_cnt/g_bnsum/g_bnsq all-zero (CLEAN tail
// in the final kernel), matching first-call zero-init. g_dinv/g_rowptr/g_fill/
// g_edge/g_h* are fully rewritten every call.
__device__ float g_deg[NN];                 // weighted in-degree (excl. self loop)
__device__ float g_dinv[NN];
__device__ int   g_cnt[NN];
__device__ int   g_fill[NN];                // scan_c seeds with prefix; fill bumps
__device__ int   g_rowptr[NN + 1];          // exclusive prefix; rowptr[N] = E
__device__ unsigned long long g_edge[EE];   // packed: (w_bits<<32) | src
__device__ __half g_h1[(size_t)NN * DF];    // dinv-scaled layer-1 features (fp16)
__device__ float  g_ha[(size_t)NN * DF];    // aggregated layer-1 output (fp32)
__device__ __half g_h2[(size_t)NN * DF];    // dinv-scaled layer-2 features (fp16)
__device__ float g_bnsum[DF];
__device__ float g_bnsq[DF];
__device__ int   g_part[128];

// ---------------- edge pass 1: weighted in-degree + per-dst edge count -----
__global__ void k_edge_deg(const int* __restrict__ ei,
                           const float* __restrict__ w, int E) {
    int e4 = (blockIdx.x * blockDim.x + threadIdx.x) * 4;
    if (e4 + 3 < E) {
        int4   d4 = *(const int4*)&ei[E + e4];
        float4 w4 = *(const float4*)&w[e4];
        atomicAdd(&g_deg[d4.x], w4.x); atomicAdd(&g_cnt[d4.x], 1);
        atomicAdd(&g_deg[d4.y], w4.y); atomicAdd(&g_cnt[d4.y], 1);
        atomicAdd(&g_deg[d4.z], w4.z); atomicAdd(&g_cnt[d4.z], 1);
        atomicAdd(&g_deg[d4.w], w4.w); atomicAdd(&g_cnt[d4.w], 1);
    } else {
        for (int e = e4; e < E; e++) {
            int d = ei[E + e];
            atomicAdd(&g_deg[d], w[e]);
            atomicAdd(&g_cnt[d], 1);
        }
    }
}

// ---------------- scan stage A: dinv + per-block sums ----------------------
__global__ void k_scan_a(int n) {
    __shared__ int s[1024];
    int t = threadIdx.x;
    int i = blockIdx.x * 1024 + t;
    if (i < n) g_dinv[i] = rsqrtf(g_deg[i] + 1.0f);   // +1 = self loop
    s[t] = (i < n) ? g_cnt[i] : 0;
    __syncthreads();
    for (int off = 512; off > 0; off >>= 1) {
        if (t < off) s[t] += s[t + off];
        __syncthreads();
    }
    if (t == 0) g_part[blockIdx.x] = s[0];
}

// ---------------- scan stage B: inline partial-prefix + local scan ---------
__global__ void k_scan_c(int n, int nb) {
    __shared__ int s[1024];
    __shared__ int sp[128];
    int t = threadIdx.x;
    int i = blockIdx.x * 1024 + t;

    if (t < 128) sp[t] = (t < nb) ? g_part[t] : 0;
    __syncthreads();
    #pragma unroll
    for (int off = 1; off < 128; off <<= 1) {
        int a = (t < 128 && t >= off) ? sp[t - off] : 0;
        __syncthreads();
        if (t < 128) sp[t] += a;
        __syncthreads();
    }

    int v = (i < n) ? g_cnt[i] : 0;
    s[t] = v;
    __syncthreads();
    for (int off = 1; off < 1024; off <<= 1) {
        int a = (t >= off) ? s[t - off] : 0;
        __syncthreads();
        s[t] += a;
        __syncthreads();
    }
    int bp = (blockIdx.x > 0) ? sp[blockIdx.x - 1] : 0;
    if (i < n) {
        int p = bp + s[t] - v;         // exclusive prefix
        g_rowptr[i] = p;
        g_fill[i]   = p;               // seed fill cursor
    }
    if (i == n - 1) g_rowptr[n] = bp + s[t];   // total = E
}

// ---------------- edge pass 2: fill CSR (raw weight; no gathers) -----------
__global__ void k_fill(const int* __restrict__ ei,
                       const float* __restrict__ w, int E) {
    int e = blockIdx.x * blockDim.x + threadIdx.x;
    if (e < E) {
        int s = ei[e];
        int d = ei[E + e];
        int slot = atomicAdd(&g_fill[d], 1);
        g_edge[slot] = ((unsigned long long)__float_as_uint(w[e]) << 32) |
                       (unsigned long long)(unsigned)s;
    }
}

// ---------------- GEMM: Yh[N,64] = dinv .* (f(X)[N,64] @ W[64,64]) (fp16) ---
// BN=true: input transform y = relu(a[k]*x + c[k]); a,c computed inline from
// batch stats (redundant per block, 64 threads, trivial).
// Epilogue scales each row by dinv[row] and stores fp16.
template <bool BN>
__global__ void __launch_bounds__(256) k_gemm(const float* __restrict__ X,
                                              const float* __restrict__ W,
                                              __half* __restrict__ Yh, int n,
                                              const float* __restrict__ gamma,
                                              const float* __restrict__ beta,
                                              float invn) {
    __shared__ __align__(16) float sW[64][64];
    __shared__ __align__(16) float sA[64];
    __shared__ __align__(16) float sC[64];
    int tid = threadIdx.x;

    {   // load W (4096 floats) cooperatively
        const float4* W4 = (const float4*)W;
        float4* sW4 = (float4*)&sW[0][0];
        #pragma unroll
        for (int i = 0; i < 4; i++) sW4[tid + 256 * i] = W4[tid + 256 * i];
    }
    if (BN && tid < 64) {
        float mu   = g_bnsum[tid] * invn;
        float var  = g_bnsq[tid] * invn - mu * mu;
        float a    = gamma[tid] * rsqrtf(var + EPSV);
        sA[tid] = a;
        sC[tid] = beta[tid] - mu * a;
    }
    __syncthreads();

    int rg = tid >> 3;                   // 0..31
    int cg = tid & 7;                    // 0..7
    int rbase = blockIdx.x * 128 + rg;   // rows rbase + 32*rr

    float acc[8][8];
    #pragma unroll
    for (int a = 0; a < 8; a++)
        #pragma unroll
        for (int b = 0; b < 8; b++) acc[a][b] = 0.0f;

    const float4* X4 = (const float4*)X;

    #pragma unroll
    for (int k4 = 0; k4 < 16; k4++) {
        float4 xv[8];
        #pragma unroll
        for (int rr = 0; rr < 8; rr++) {
            int r = rbase + 32 * rr;
            xv[rr] = (r < n) ? X4[(size_t)r * 16 + k4] : make_float4(0.f, 0.f, 0.f, 0.f);
        }
        if (BN) {
            float4 a4 = ((const float4*)sA)[k4];
            float4 c4 = ((const float4*)sC)[k4];
            #pragma unroll
            for (int rr = 0; rr < 8; rr++) {
                xv[rr].x = fmaxf(fmaf(a4.x, xv[rr].x, c4.x), 0.0f);
                xv[rr].y = fmaxf(fmaf(a4.y, xv[rr].y, c4.y), 0.0f);
                xv[rr].z = fmaxf(fmaf(a4.z, xv[rr].z, c4.z), 0.0f);
                xv[rr].w = fmaxf(fmaf(a4.w, xv[rr].w, c4.w), 0.0f);
            }
        }
        #pragma unroll
        for (int kk = 0; kk < 4; kk++) {
            const float* wrow = &sW[k4 * 4 + kk][cg * 8];
            float4 w0 = *(const float4*)(wrow);
            float4 w1 = *(const float4*)(wrow + 4);
            #pragma unroll
            for (int rr = 0; rr < 8; rr++) {
                float xk = ((const float*)&xv[rr])[kk];
                acc[rr][0] = fmaf(xk, w0.x, acc[rr][0]);
                acc[rr][1] = fmaf(xk, w0.y, acc[rr][1]);
                acc[rr][2] = fmaf(xk, w0.z, acc[rr][2]);
                acc[rr][3] = fmaf(xk, w0.w, acc[rr][3]);
                acc[rr][4] = fmaf(xk, w1.x, acc[rr][4]);
                acc[rr][5] = fmaf(xk, w1.y, acc[rr][5]);
                acc[rr][6] = fmaf(xk, w1.z, acc[rr][6]);
                acc[rr][7] = fmaf(xk, w1.w, acc[rr][7]);
            }
        }
    }

    #pragma unroll
    for (int rr = 0; rr < 8; rr++) {
        int r = rbase + 32 * rr;
        if (r < n) {
            float dv = g_dinv[r];
            __half2 p0 = __floats2half2_rn(acc[rr][0] * dv, acc[rr][1] * dv);
            __half2 p1 = __floats2half2_rn(acc[rr][2] * dv, acc[rr][3] * dv);
            __half2 p2 = __floats2half2_rn(acc[rr][4] * dv, acc[rr][5] * dv);
            __half2 p3 = __floats2half2_rn(acc[rr][6] * dv, acc[rr][7] * dv);
            uint4 st;
            st.x = *(unsigned*)&p0; st.y = *(unsigned*)&p1;
            st.z = *(unsigned*)&p2; st.w = *(unsigned*)&p3;
            ((uint4*)(Yh + (size_t)r * 64))[cg] = st;
        }
    }
}

// ---------------- aggregation: 16 lanes per node, 4 feats (8B fp16)/lane ---
// out[i] = dinv[i] * ( H'[i] + sum_e w_e * H'[src_e] ) + bias   (fp32 accum)
// STATS: per-feature sum/sumsq via conflict-free smem transpose-reduce.
// CLEAN: tail cleanup restoring the all-zero scratch invariant.
template <bool STATS, bool CLEAN>
__global__ void __launch_bounds__(256) k_agg(const __half* __restrict__ H,
                                             const float* __restrict__ bias,
                                             float* __restrict__ out, int n) {
    int tid  = threadIdx.x;
    int sub  = tid >> 4;        // 0..15 node slot
    int l4   = tid & 15;        // feature group (4 halves = 8B)
    int i    = blockIdx.x * 16 + sub;

    float4 acc = make_float4(0.f, 0.f, 0.f, 0.f);
    if (i < n) {
        {   // self term (weight 1 in the dinv-scaled domain)
            uint2 u = ((const uint2*)(H + (size_t)i * 64))[l4];
            float2 f0 = __half22float2(*(const __half2*)&u.x);
            float2 f1 = __half22float2(*(const __half2*)&u.y);
            acc.x = f0.x; acc.y = f0.y; acc.z = f1.x; acc.w = f1.y;
        }

        int e   = g_rowptr[i];
        int end = g_rowptr[i + 1];

        for (; e + 4 <= end; e += 4) {
            unsigned long long p0 = g_edge[e];
            unsigned long long p1 = g_edge[e + 1];
            unsigned long long p2 = g_edge[e + 2];
            unsigned long long p3 = g_edge[e + 3];
            uint2 u0 = ((const uint2*)(H + (size_t)(unsigned)p0 * 64))[l4];
            uint2 u1 = ((const uint2*)(H + (size_t)(unsigned)p1 * 64))[l4];
            uint2 u2 = ((const uint2*)(H + (size_t)(unsigned)p2 * 64))[l4];
            uint2 u3 = ((const uint2*)(H + (size_t)(unsigned)p3 * 64))[l4];
            float w0 = __uint_as_float((unsigned)(p0 >> 32));
            float w1 = __uint_as_float((unsigned)(p1 >> 32));
            float w2 = __uint_as_float((unsigned)(p2 >> 32));
            float w3 = __uint_as_float((unsigned)(p3 >> 32));
            float2 a0 = __half22float2(*(const __half2*)&u0.x);
            float2 b0 = __half22float2(*(const __half2*)&u0.y);
            float2 a1 = __half22float2(*(const __half2*)&u1.x);
            float2 b1 = __half22float2(*(const __half2*)&u1.y);
            float2 a2 = __half22float2(*(const __half2*)&u2.x);
            float2 b2 = __half22float2(*(const __half2*)&u2.y);
            float2 a3 = __half22float2(*(const __half2*)&u3.x);
            float2 b3 = __half22float2(*(const __half2*)&u3.y);
            acc.x = fmaf(w0, a0.x, acc.x); acc.y = fmaf(w0, a0.y, acc.y);
            acc.z = fmaf(w0, b0.x, acc.z); acc.w = fmaf(w0, b0.y, acc.w);
            acc.x = fmaf(w1, a1.x, acc.x); acc.y = fmaf(w1, a1.y, acc.y);
            acc.z = fmaf(w1, b1.x, acc.z); acc.w = fmaf(w1, b1.y, acc.w);
            acc.x = fmaf(w2, a2.x, acc.x); acc.y = fmaf(w2, a2.y, acc.y);
            acc.z = fmaf(w2, b2.x, acc.z); acc.w = fmaf(w2, b2.y, acc.w);
            acc.x = fmaf(w3, a3.x, acc.x); acc.y = fmaf(w3, a3.y, acc.y);
            acc.z = fmaf(w3, b3.x, acc.z); acc.w = fmaf(w3, b3.y, acc.w);
        }
        for (; e < end; e++) {
            unsigned long long p0 = g_edge[e];
            uint2 u0 = ((const uint2*)(H + (size_t)(unsigned)p0 * 64))[l4];
            float w0 = __uint_as_float((unsigned)(p0 >> 32));
            float2 a0 = __half22float2(*(const __half2*)&u0.x);
            float2 b0 = __half22float2(*(const __half2*)&u0.y);
            acc.x = fmaf(w0, a0.x, acc.x); acc.y = fmaf(w0, a0.y, acc.y);
            acc.z = fmaf(w0, b0.x, acc.z); acc.w = fmaf(w0, b0.y, acc.w);
        }

        float dv = g_dinv[i];
        float4 b = ((const float4*)bias)[l4];
        float4 o = make_float4(fmaf(dv, acc.x, b.x), fmaf(dv, acc.y, b.y),
                               fmaf(dv, acc.z, b.z), fmaf(dv, acc.w, b.w));
        ((float4*)(out + (size_t)i * 64))[l4] = o;
        acc = o;   // stats are over the biased output
    } else {
        acc = make_float4(0.f, 0.f, 0.f, 0.f);
    }

    if (STATS) {
        __shared__ __align__(16) float sacc[16][80];   // 80-pad: conflict-free
        ((float4*)&sacc[sub][l4 * 4])[0] = acc;
        __syncthreads();
        if (tid < 64) {
            float s = 0.f, q = 0.f;
            #pragma unroll
            for (int k = 0; k < 16; k++) {
                float v = sacc[k][tid];
                s += v;
                q += v * v;
            }
            atomicAdd(&g_bnsum[tid], s);
            atomicAdd(&g_bnsq[tid],  q);
        }
    }

    if (CLEAN) {
        // restore all-zero invariant (g_fill/g_rowptr/g_dinv/g_edge are fully
        // rewritten next call; only the accumulated arrays need zeroing).
        int g = blockIdx.x * 256 + tid;
        if (g < n) { g_deg[g] = 0.0f; g_cnt[g] = 0; }
        if (g < DF) { g_bnsum[g] = 0.0f; g_bnsq[g] = 0.0f; }
    }
}

// ---------------------------------------------------------------------------
extern "C" void kernel_launch(void* const* d_in, const int* in_sizes, int n_in,
                              void* d_out, int out_size) {
    const float* x     = (const float*)d_in[0];
    const int*   ei    = (const int*)d_in[1];
    const float* ew    = (const float*)d_in[2];
    const float* W1    = (const float*)d_in[3];
    const float* b1    = (const float*)d_in[4];
    const float* gamma = (const float*)d_in[5];
    const float* beta  = (const float*)d_in[6];
    const float* W2    = (const float*)d_in[7];
    const float* b2    = (const float*)d_in[8];

    int N = in_sizes[0] / DF;
    int E = in_sizes[2];
    if (N > NN || E > EE) return;

    __half *p_h1, *p_h2;
    float *p_ha;
    cudaGetSymbolAddress((void**)&p_h1, g_h1);
    cudaGetSymbolAddress((void**)&p_ha, g_ha);
    cudaGetSymbolAddress((void**)&p_h2, g_h2);

    int nb = (N + 1023) / 1024;
    float invn = 1.0f / (float)N;

    k_edge_deg<<<(E + 1023) / 1024, 256>>>(ei, ew, E);
    k_scan_a<<<nb, 1024>>>(N);
    k_scan_c<<<nb, 1024>>>(N, nb);
    k_fill<<<(E + 255) / 256, 256>>>(ei, ew, E);

    k_gemm<false><<<(N + 127) / 128, 256>>>(x, W1, p_h1, N, nullptr, nullptr, 0.f);
    k_agg<true, false><<<(N + 15) / 16, 256>>>(p_h1, b1, p_ha, N);
    k_gemm<true><<<(N + 127) / 128, 256>>>(p_ha, W2, p_h2, N, gamma, beta, invn);
    k_agg<false, true><<<(N + 15) / 16, 256>>>(p_h2, b2, (float*)d_out, N);
}

// round 5
// speedup vs baseline: 1.3180x; 1.0629x over previous
#include <cuda_runtime.h>
#include <cuda_fp16.h>

#define DF   64
#define NN   100000
#define EE   1600000
#define EPSV 1e-5f
#define WSCALE 268435456.0f          // 2^28 fixed-point weight scale
#define WINV   (1.0f / 268435456.0f)

// ---------------- scratch (device globals; zero-initialized at load) -------
// Invariant: every call leaves g_degcnt/g_bnsum/g_bnsq all-zero (CLEAN tail in
// the final kernel), matching first-call zero-init. Everything else is fully
// rewritten every call.
__device__ unsigned long long g_degcnt[NN]; // (cnt<<48) | fx28 weighted degree
__device__ float g_dinv[NN];
__device__ int   g_fill[NN];                // scan_c seeds with prefix; fill bumps
__device__ int   g_rowptr[NN + 1];          // exclusive prefix; rowptr[N] = E
__device__ unsigned long long g_edge[EE];   // packed: (w_bits<<32) | src
__device__ __half g_h1[(size_t)NN * DF];    // dinv-scaled layer-1 features (fp16)
__device__ float  g_ha[(size_t)NN * DF];    // aggregated layer-1 output (fp32)
__device__ __half g_h2[(size_t)NN * DF];    // dinv-scaled layer-2 features (fp16)
__device__ float g_bnsum[DF];
__device__ float g_bnsq[DF];
__device__ int   g_part[128];

__device__ __forceinline__ unsigned long long pack_dc(float w) {
    return (1ULL << 48) | (unsigned long long)(fmaf(w, WSCALE, 0.5f));
}

// ---------------- edge pass 1: single packed atomic per edge ---------------
__global__ void k_edge_deg(const int* __restrict__ ei,
                           const float* __restrict__ w, int E) {
    int e4 = (blockIdx.x * blockDim.x + threadIdx.x) * 4;
    if (e4 + 3 < E) {
        int4   d4 = *(const int4*)&ei[E + e4];
        float4 w4 = *(const float4*)&w[e4];
        atomicAdd(&g_degcnt[d4.x], pack_dc(w4.x));
        atomicAdd(&g_degcnt[d4.y], pack_dc(w4.y));
        atomicAdd(&g_degcnt[d4.z], pack_dc(w4.z));
        atomicAdd(&g_degcnt[d4.w], pack_dc(w4.w));
    } else {
        for (int e = e4; e < E; e++)
            atomicAdd(&g_degcnt[ei[E + e]], pack_dc(w[e]));
    }
}
__global__ void k_edge_deg_s(const int* __restrict__ ei,
                             const float* __restrict__ w, int E) {
    int e = blockIdx.x * blockDim.x + threadIdx.x;
    if (e < E) atomicAdd(&g_degcnt[ei[E + e]], pack_dc(w[e]));
}

// ---------------- scan stage A: dinv + per-block sums ----------------------
__global__ void k_scan_a(int n) {
    __shared__ int s[1024];
    int t = threadIdx.x;
    int i = blockIdx.x * 1024 + t;
    int cnt = 0;
    if (i < n) {
        unsigned long long p = g_degcnt[i];
        cnt = (int)(p >> 48);
        float deg = (float)(long long)(p & 0xFFFFFFFFFFFFULL) * WINV;
        g_dinv[i] = rsqrtf(deg + 1.0f);        // +1 = self loop
    }
    s[t] = cnt;
    __syncthreads();
    for (int off = 512; off > 0; off >>= 1) {
        if (t < off) s[t] += s[t + off];
        __syncthreads();
    }
    if (t == 0) g_part[blockIdx.x] = s[0];
}

// ---------------- scan stage B: inline partial-prefix + local scan ---------
__global__ void k_scan_c(int n, int nb) {
    __shared__ int s[1024];
    __shared__ int sp[128];
    int t = threadIdx.x;
    int i = blockIdx.x * 1024 + t;

    if (t < 128) sp[t] = (t < nb) ? g_part[t] : 0;
    __syncthreads();
    #pragma unroll
    for (int off = 1; off < 128; off <<= 1) {
        int a = (t < 128 && t >= off) ? sp[t - off] : 0;
        __syncthreads();
        if (t < 128) sp[t] += a;
        __syncthreads();
    }

    int v = (i < n) ? (int)(g_degcnt[i] >> 48) : 0;
    s[t] = v;
    __syncthreads();
    for (int off = 1; off < 1024; off <<= 1) {
        int a = (t >= off) ? s[t - off] : 0;
        __syncthreads();
        s[t] += a;
        __syncthreads();
    }
    int bp = (blockIdx.x > 0) ? sp[blockIdx.x - 1] : 0;
    if (i < n) {
        int p = bp + s[t] - v;         // exclusive prefix
        g_rowptr[i] = p;
        g_fill[i]   = p;               // seed fill cursor
    }
    if (i == n - 1) g_rowptr[n] = bp + s[t];   // total = E
}

// ---------------- edge pass 2: fill CSR (raw weight; no gathers) -----------
__device__ __forceinline__ unsigned long long pack_edge(float w, int s) {
    return ((unsigned long long)__float_as_uint(w) << 32) |
           (unsigned long long)(unsigned)s;
}
__global__ void k_fill(const int* __restrict__ ei,
                       const float* __restrict__ w, int E) {
    int e2 = (blockIdx.x * blockDim.x + threadIdx.x) * 2;
    if (e2 + 1 < E) {
        int2   sv = *(const int2*)&ei[e2];
        int2   dv = *(const int2*)&ei[E + e2];
        float2 wv = *(const float2*)&w[e2];
        int slot0 = atomicAdd(&g_fill[dv.x], 1);
        int slot1 = atomicAdd(&g_fill[dv.y], 1);
        g_edge[slot0] = pack_edge(wv.x, sv.x);
        g_edge[slot1] = pack_edge(wv.y, sv.y);
    } else if (e2 < E) {
        int slot = atomicAdd(&g_fill[ei[E + e2]], 1);
        g_edge[slot] = pack_edge(w[e2], ei[e2]);
    }
}
__global__ void k_fill_s(const int* __restrict__ ei,
                         const float* __restrict__ w, int E) {
    int e = blockIdx.x * blockDim.x + threadIdx.x;
    if (e < E) {
        int slot = atomicAdd(&g_fill[ei[E + e]], 1);
        g_edge[slot] = pack_edge(w[e], ei[e]);
    }
}

// ---------------- GEMM: Yh[N,64] = dinv .* (f(X)[N,64] @ W[64,64]) (fp16) ---
template <bool BN>
__global__ void __launch_bounds__(256) k_gemm(const float* __restrict__ X,
                                              const float* __restrict__ W,
                                              __half* __restrict__ Yh, int n,
                                              const float* __restrict__ gamma,
                                              const float* __restrict__ beta,
                                              float invn) {
    __shared__ __align__(16) float sW[64][64];
    __shared__ __align__(16) float sA[64];
    __shared__ __align__(16) float sC[64];
    int tid = threadIdx.x;

    {   // load W (4096 floats) cooperatively
        const float4* W4 = (const float4*)W;
        float4* sW4 = (float4*)&sW[0][0];
        #pragma unroll
        for (int i = 0; i < 4; i++) sW4[tid + 256 * i] = W4[tid + 256 * i];
    }
    if (BN && tid < 64) {
        float mu   = g_bnsum[tid] * invn;
        float var  = g_bnsq[tid] * invn - mu * mu;
        float a    = gamma[tid] * rsqrtf(var + EPSV);
        sA[tid] = a;
        sC[tid] = beta[tid] - mu * a;
    }
    __syncthreads();

    int rg = tid >> 3;                   // 0..31
    int cg = tid & 7;                    // 0..7
    int rbase = blockIdx.x * 128 + rg;   // rows rbase + 32*rr

    float acc[8][8];
    #pragma unroll
    for (int a = 0; a < 8; a++)
        #pragma unroll
        for (int b = 0; b < 8; b++) acc[a][b] = 0.0f;

    const float4* X4 = (const float4*)X;

    #pragma unroll
    for (int k4 = 0; k4 < 16; k4++) {
        float4 xv[8];
        #pragma unroll
        for (int rr = 0; rr < 8; rr++) {
            int r = rbase + 32 * rr;
            xv[rr] = (r < n) ? X4[(size_t)r * 16 + k4] : make_float4(0.f, 0.f, 0.f, 0.f);
        }
        if (BN) {
            float4 a4 = ((const float4*)sA)[k4];
            float4 c4 = ((const float4*)sC)[k4];
            #pragma unroll
            for (int rr = 0; rr < 8; rr++) {
                xv[rr].x = fmaxf(fmaf(a4.x, xv[rr].x, c4.x), 0.0f);
                xv[rr].y = fmaxf(fmaf(a4.y, xv[rr].y, c4.y), 0.0f);
                xv[rr].z = fmaxf(fmaf(a4.z, xv[rr].z, c4.z), 0.0f);
                xv[rr].w = fmaxf(fmaf(a4.w, xv[rr].w, c4.w), 0.0f);
            }
        }
        #pragma unroll
        for (int kk = 0; kk < 4; kk++) {
            const float* wrow = &sW[k4 * 4 + kk][cg * 8];
            float4 w0 = *(const float4*)(wrow);
            float4 w1 = *(const float4*)(wrow + 4);
            #pragma unroll
            for (int rr = 0; rr < 8; rr++) {
                float xk = ((const float*)&xv[rr])[kk];
                acc[rr][0] = fmaf(xk, w0.x, acc[rr][0]);
                acc[rr][1] = fmaf(xk, w0.y, acc[rr][1]);
                acc[rr][2] = fmaf(xk, w0.z, acc[rr][2]);
                acc[rr][3] = fmaf(xk, w0.w, acc[rr][3]);
                acc[rr][4] = fmaf(xk, w1.x, acc[rr][4]);
                acc[rr][5] = fmaf(xk, w1.y, acc[rr][5]);
                acc[rr][6] = fmaf(xk, w1.z, acc[rr][6]);
                acc[rr][7] = fmaf(xk, w1.w, acc[rr][7]);
            }
        }
    }

    #pragma unroll
    for (int rr = 0; rr < 8; rr++) {
        int r = rbase + 32 * rr;
        if (r < n) {
            float dv = g_dinv[r];
            __half2 p0 = __floats2half2_rn(acc[rr][0] * dv, acc[rr][1] * dv);
            __half2 p1 = __floats2half2_rn(acc[rr][2] * dv, acc[rr][3] * dv);
            __half2 p2 = __floats2half2_rn(acc[rr][4] * dv, acc[rr][5] * dv);
            __half2 p3 = __floats2half2_rn(acc[rr][6] * dv, acc[rr][7] * dv);
            uint4 st;
            st.x = *(unsigned*)&p0; st.y = *(unsigned*)&p1;
            st.z = *(unsigned*)&p2; st.w = *(unsigned*)&p3;
            ((uint4*)(Yh + (size_t)r * 64))[cg] = st;
        }
    }
}

// ---------------- aggregation: 8 lanes/node, 8 feats (16B fp16) per lane ---
// out[i] = dinv[i] * ( H'[i] + sum_e w_e * H'[src_e] ) + bias   (fp32 accum)
// 32 nodes per 256-thread block; 4 independent gather chains per warp.
template <bool STATS, bool CLEAN>
__global__ void __launch_bounds__(256) k_agg(const __half* __restrict__ H,
                                             const float* __restrict__ bias,
                                             float* __restrict__ out, int n) {
    int tid = threadIdx.x;
    int sub = tid >> 3;         // 0..31 node slot
    int l8  = tid & 7;          // feature group (8 halves = 16B)
    int i   = blockIdx.x * 32 + sub;

    float acc[8];
    #pragma unroll
    for (int k = 0; k < 8; k++) acc[k] = 0.0f;

    if (i < n) {
        {   // self term (weight 1 in the dinv-scaled domain)
            uint4 u = ((const uint4*)(H + (size_t)i * 64))[l8];
            float2 f0 = __half22float2(*(const __half2*)&u.x);
            float2 f1 = __half22float2(*(const __half2*)&u.y);
            float2 f2 = __half22float2(*(const __half2*)&u.z);
            float2 f3 = __half22float2(*(const __half2*)&u.w);
            acc[0] = f0.x; acc[1] = f0.y; acc[2] = f1.x; acc[3] = f1.y;
            acc[4] = f2.x; acc[5] = f2.y; acc[6] = f3.x; acc[7] = f3.y;
        }

        int e   = g_rowptr[i];
        int end = g_rowptr[i + 1];

        for (; e + 4 <= end; e += 4) {
            unsigned long long p0 = g_edge[e];
            unsigned long long p1 = g_edge[e + 1];
            unsigned long long p2 = g_edge[e + 2];
            unsigned long long p3 = g_edge[e + 3];
            uint4 u0 = ((const uint4*)(H + (size_t)(unsigned)p0 * 64))[l8];
            uint4 u1 = ((const uint4*)(H + (size_t)(unsigned)p1 * 64))[l8];
            uint4 u2 = ((const uint4*)(H + (size_t)(unsigned)p2 * 64))[l8];
            uint4 u3 = ((const uint4*)(H + (size_t)(unsigned)p3 * 64))[l8];
            float w0 = __uint_as_float((unsigned)(p0 >> 32));
            float w1 = __uint_as_float((unsigned)(p1 >> 32));
            float w2 = __uint_as_float((unsigned)(p2 >> 32));
            float w3 = __uint_as_float((unsigned)(p3 >> 32));
            #pragma unroll
            for (int q = 0; q < 4; q++) {
                unsigned lo = (&u0.x)[q], l1 = (&u1.x)[q], l2v = (&u2.x)[q], l3 = (&u3.x)[q];
                float2 f0 = __half22float2(*(const __half2*)&lo);
                float2 f1 = __half22float2(*(const __half2*)&l1);
                float2 f2 = __half22float2(*(const __half2*)&l2v);
                float2 f3 = __half22float2(*(const __half2*)&l3);
                acc[2*q]   = fmaf(w0, f0.x, acc[2*q]);
                acc[2*q+1] = fmaf(w0, f0.y, acc[2*q+1]);
                acc[2*q]   = fmaf(w1, f1.x, acc[2*q]);
                acc[2*q+1] = fmaf(w1, f1.y, acc[2*q+1]);
                acc[2*q]   = fmaf(w2, f2.x, acc[2*q]);
                acc[2*q+1] = fmaf(w2, f2.y, acc[2*q+1]);
                acc[2*q]   = fmaf(w3, f3.x, acc[2*q]);
                acc[2*q+1] = fmaf(w3, f3.y, acc[2*q+1]);
            }
        }
        for (; e < end; e++) {
            unsigned long long p0 = g_edge[e];
            uint4 u0 = ((const uint4*)(H + (size_t)(unsigned)p0 * 64))[l8];
            float w0 = __uint_as_float((unsigned)(p0 >> 32));
            #pragma unroll
            for (int q = 0; q < 4; q++) {
                unsigned lo = (&u0.x)[q];
                float2 f0 = __half22float2(*(const __half2*)&lo);
                acc[2*q]   = fmaf(w0, f0.x, acc[2*q]);
                acc[2*q+1] = fmaf(w0, f0.y, acc[2*q+1]);
            }
        }

        float dv = g_dinv[i];
        const float4* B4 = (const float4*)bias;
        float4 b0 = B4[l8 * 2], b1 = B4[l8 * 2 + 1];
        float4 o0 = make_float4(fmaf(dv, acc[0], b0.x), fmaf(dv, acc[1], b0.y),
                                fmaf(dv, acc[2], b0.z), fmaf(dv, acc[3], b0.w));
        float4 o1 = make_float4(fmaf(dv, acc[4], b1.x), fmaf(dv, acc[5], b1.y),
                                fmaf(dv, acc[6], b1.z), fmaf(dv, acc[7], b1.w));
        float4* O4 = (float4*)(out + (size_t)i * 64);
        O4[l8 * 2] = o0; O4[l8 * 2 + 1] = o1;
        acc[0]=o0.x; acc[1]=o0.y; acc[2]=o0.z; acc[3]=o0.w;
        acc[4]=o1.x; acc[5]=o1.y; acc[6]=o1.z; acc[7]=o1.w;
    } else {
        #pragma unroll
        for (int k = 0; k < 8; k++) acc[k] = 0.0f;
    }

    if (STATS) {
        __shared__ __align__(16) float sacc[32][68];
        float4* row = (float4*)&sacc[sub][l8 * 8];
        row[0] = make_float4(acc[0], acc[1], acc[2], acc[3]);
        row[1] = make_float4(acc[4], acc[5], acc[6], acc[7]);
        __syncthreads();
        if (tid < 64) {
            float s = 0.f, q = 0.f;
            #pragma unroll
            for (int k = 0; k < 32; k++) {
                float v = sacc[k][tid];
                s += v;
                q += v * v;
            }
            atomicAdd(&g_bnsum[tid], s);
            atomicAdd(&g_bnsq[tid],  q);
        }
    }

    if (CLEAN) {
        // restore all-zero invariant (everything else fully rewritten per call)
        int g = blockIdx.x * 256 + tid;
        if (g < n) g_degcnt[g] = 0ULL;
        if (g < DF) { g_bnsum[g] = 0.0f; g_bnsq[g] = 0.0f; }
    }
}

// ---------------------------------------------------------------------------
extern "C" void kernel_launch(void* const* d_in, const int* in_sizes, int n_in,
                              void* d_out, int out_size) {
    const float* x     = (const float*)d_in[0];
    const int*   ei    = (const int*)d_in[1];
    const float* ew    = (const float*)d_in[2];
    const float* W1    = (const float*)d_in[3];
    const float* b1    = (const float*)d_in[4];
    const float* gamma = (const float*)d_in[5];
    const float* beta  = (const float*)d_in[6];
    const float* W2    = (const float*)d_in[7];
    const float* b2    = (const float*)d_in[8];

    int N = in_sizes[0] / DF;
    int E = in_sizes[2];
    if (N > NN || E > EE) return;

    __half *p_h1, *p_h2;
    float *p_ha;
    cudaGetSymbolAddress((void**)&p_h1, g_h1);
    cudaGetSymbolAddress((void**)&p_ha, g_ha);
    cudaGetSymbolAddress((void**)&p_h2, g_h2);

    int nb = (N + 1023) / 1024;
    float invn = 1.0f / (float)N;

    if ((E & 3) == 0)
        k_edge_deg<<<(E / 4 + 255) / 256, 256>>>(ei, ew, E);
    else
        k_edge_deg_s<<<(E + 255) / 256, 256>>>(ei, ew, E);
    k_scan_a<<<nb, 1024>>>(N);
    k_scan_c<<<nb, 1024>>>(N, nb);
    if ((E & 1) == 0)
        k_fill<<<(E / 2 + 255) / 256, 256>>>(ei, ew, E);
    else
        k_fill_s<<<(E + 255) / 256, 256>>>(ei, ew, E);

    k_gemm<false><<<(N + 127) / 128, 256>>>(x, W1, p_h1, N, nullptr, nullptr, 0.f);
    k_agg<true, false><<<(N + 31) / 32, 256>>>(p_h1, b1, p_ha, N);
    k_gemm<true><<<(N + 127) / 128, 256>>>(p_ha, W2, p_h2, N, gamma, beta, invn);
    k_agg<false, true><<<(N + 31) / 32, 256>>>(p_h2, b2, (float*)d_out, N);
}

// round 6
// speedup vs baseline: 1.3548x; 1.0279x over previous
#include <cuda_runtime.h>
#include <cuda_fp16.h>

#define DF   64
#define NN   100000
#define EE   1600000
#define EPSV 1e-5f
#define WSCALE 268435456.0f          // 2^28 fixed-point weight scale
#define WINV   (1.0f / 268435456.0f)

// ---------------- scratch (device globals; zero-initialized at load) -------
// Invariant: every call leaves g_degcnt/g_bnsum/g_bnsq all-zero (CLEAN tail in
// the final kernel), matching first-call zero-init. Everything else is fully
// rewritten every call.
__device__ unsigned long long g_degcnt[NN]; // (cnt<<48) | fx28 weighted degree
__device__ float g_dinv[NN];
__device__ int   g_fill[NN];                // scan_c seeds with prefix; fill bumps
__device__ int   g_rowptr[NN + 1];          // exclusive prefix; rowptr[N] = E
__device__ unsigned long long g_edge[EE];   // packed: (w_bits<<32) | src
__device__ __half g_h1[(size_t)NN * DF];    // dinv-scaled layer-1 features (fp16)
__device__ float  g_ha[(size_t)NN * DF];    // aggregated layer-1 output (fp32)
__device__ __half g_h2[(size_t)NN * DF];    // dinv-scaled layer-2 features (fp16)
__device__ float g_bnsum[DF];
__device__ float g_bnsq[DF];
__device__ int   g_part[128];

__device__ __forceinline__ unsigned long long pack_dc(float w) {
    return (1ULL << 48) | (unsigned long long)(fmaf(w, WSCALE, 0.5f));
}

// ---------------- edge pass 1: single packed atomic per edge ---------------
__global__ void k_edge_deg(const int* __restrict__ ei,
                           const float* __restrict__ w, int E) {
    int e4 = (blockIdx.x * blockDim.x + threadIdx.x) * 4;
    if (e4 + 3 < E) {
        int4   d4 = *(const int4*)&ei[E + e4];
        float4 w4 = *(const float4*)&w[e4];
        atomicAdd(&g_degcnt[d4.x], pack_dc(w4.x));
        atomicAdd(&g_degcnt[d4.y], pack_dc(w4.y));
        atomicAdd(&g_degcnt[d4.z], pack_dc(w4.z));
        atomicAdd(&g_degcnt[d4.w], pack_dc(w4.w));
    } else {
        for (int e = e4; e < E; e++)
            atomicAdd(&g_degcnt[ei[E + e]], pack_dc(w[e]));
    }
}
__global__ void k_edge_deg_s(const int* __restrict__ ei,
                             const float* __restrict__ w, int E) {
    int e = blockIdx.x * blockDim.x + threadIdx.x;
    if (e < E) atomicAdd(&g_degcnt[ei[E + e]], pack_dc(w[e]));
}

// ---------------- scan stage A: dinv + per-block sums ----------------------
__global__ void k_scan_a(int n) {
    __shared__ int s[1024];
    int t = threadIdx.x;
    int i = blockIdx.x * 1024 + t;
    int cnt = 0;
    if (i < n) {
        unsigned long long p = g_degcnt[i];
        cnt = (int)(p >> 48);
        float deg = (float)(long long)(p & 0xFFFFFFFFFFFFULL) * WINV;
        g_dinv[i] = rsqrtf(deg + 1.0f);        // +1 = self loop
    }
    s[t] = cnt;
    __syncthreads();
    for (int off = 512; off > 0; off >>= 1) {
        if (t < off) s[t] += s[t + off];
        __syncthreads();
    }
    if (t == 0) g_part[blockIdx.x] = s[0];
}

// ---------------- scan stage B: inline partial-prefix + local scan ---------
__global__ void k_scan_c(int n, int nb) {
    __shared__ int s[1024];
    __shared__ int sp[128];
    int t = threadIdx.x;
    int i = blockIdx.x * 1024 + t;

    if (t < 128) sp[t] = (t < nb) ? g_part[t] : 0;
    __syncthreads();
    #pragma unroll
    for (int off = 1; off < 128; off <<= 1) {
        int a = (t < 128 && t >= off) ? sp[t - off] : 0;
        __syncthreads();
        if (t < 128) sp[t] += a;
        __syncthreads();
    }

    int v = (i < n) ? (int)(g_degcnt[i] >> 48) : 0;
    s[t] = v;
    __syncthreads();
    for (int off = 1; off < 1024; off <<= 1) {
        int a = (t >= off) ? s[t - off] : 0;
        __syncthreads();
        s[t] += a;
        __syncthreads();
    }
    int bp = (blockIdx.x > 0) ? sp[blockIdx.x - 1] : 0;
    if (i < n) {
        int p = bp + s[t] - v;         // exclusive prefix
        g_rowptr[i] = p;
        g_fill[i]   = p;               // seed fill cursor
    }
    if (i == n - 1) g_rowptr[n] = bp + s[t];   // total = E
}

// ---------------- edge pass 2: fill CSR (raw weight; no gathers) -----------
__device__ __forceinline__ unsigned long long pack_edge(float w, int s) {
    return ((unsigned long long)__float_as_uint(w) << 32) |
           (unsigned long long)(unsigned)s;
}
__global__ void k_fill(const int* __restrict__ ei,
                       const float* __restrict__ w, int E) {
    int e2 = (blockIdx.x * blockDim.x + threadIdx.x) * 2;
    if (e2 + 1 < E) {
        int2   sv = *(const int2*)&ei[e2];
        int2   dv = *(const int2*)&ei[E + e2];
        float2 wv = *(const float2*)&w[e2];
        int slot0 = atomicAdd(&g_fill[dv.x], 1);
        int slot1 = atomicAdd(&g_fill[dv.y], 1);
        g_edge[slot0] = pack_edge(wv.x, sv.x);
        g_edge[slot1] = pack_edge(wv.y, sv.y);
    } else if (e2 < E) {
        int slot = atomicAdd(&g_fill[ei[E + e2]], 1);
        g_edge[slot] = pack_edge(w[e2], ei[e2]);
    }
}
__global__ void k_fill_s(const int* __restrict__ ei,
                         const float* __restrict__ w, int E) {
    int e = blockIdx.x * blockDim.x + threadIdx.x;
    if (e < E) {
        int slot = atomicAdd(&g_fill[ei[E + e]], 1);
        g_edge[slot] = pack_edge(w[e], ei[e]);
    }
}

// ---------------- GEMM: Yh[N,64] = dinv .* (f(X)[N,64] @ W[64,64]) (fp16) ---
template <bool BN>
__global__ void __launch_bounds__(256) k_gemm(const float* __restrict__ X,
                                              const float* __restrict__ W,
                                              __half* __restrict__ Yh, int n,
                                              const float* __restrict__ gamma,
                                              const float* __restrict__ beta,
                                              float invn) {
    __shared__ __align__(16) float sW[64][64];
    __shared__ __align__(16) float sA[64];
    __shared__ __align__(16) float sC[64];
    int tid = threadIdx.x;

    {   // load W (4096 floats) cooperatively
        const float4* W4 = (const float4*)W;
        float4* sW4 = (float4*)&sW[0][0];
        #pragma unroll
        for (int i = 0; i < 4; i++) sW4[tid + 256 * i] = W4[tid + 256 * i];
    }
    if (BN && tid < 64) {
        float mu   = g_bnsum[tid] * invn;
        float var  = g_bnsq[tid] * invn - mu * mu;
        float a    = gamma[tid] * rsqrtf(var + EPSV);
        sA[tid] = a;
        sC[tid] = beta[tid] - mu * a;
    }
    __syncthreads();

    int rg = tid >> 3;                   // 0..31
    int cg = tid & 7;                    // 0..7
    int rbase = blockIdx.x * 128 + rg;   // rows rbase + 32*rr

    float acc[8][8];
    #pragma unroll
    for (int a = 0; a < 8; a++)
        #pragma unroll
        for (int b = 0; b < 8; b++) acc[a][b] = 0.0f;

    const float4* X4 = (const float4*)X;

    #pragma unroll
    for (int k4 = 0; k4 < 16; k4++) {
        float4 xv[8];
        #pragma unroll
        for (int rr = 0; rr < 8; rr++) {
            int r = rbase + 32 * rr;
            xv[rr] = (r < n) ? X4[(size_t)r * 16 + k4] : make_float4(0.f, 0.f, 0.f, 0.f);
        }
        if (BN) {
            float4 a4 = ((const float4*)sA)[k4];
            float4 c4 = ((const float4*)sC)[k4];
            #pragma unroll
            for (int rr = 0; rr < 8; rr++) {
                xv[rr].x = fmaxf(fmaf(a4.x, xv[rr].x, c4.x), 0.0f);
                xv[rr].y = fmaxf(fmaf(a4.y, xv[rr].y, c4.y), 0.0f);
                xv[rr].z = fmaxf(fmaf(a4.z, xv[rr].z, c4.z), 0.0f);
                xv[rr].w = fmaxf(fmaf(a4.w, xv[rr].w, c4.w), 0.0f);
            }
        }
        #pragma unroll
        for (int kk = 0; kk < 4; kk++) {
            const float* wrow = &sW[k4 * 4 + kk][cg * 8];
            float4 w0 = *(const float4*)(wrow);
            float4 w1 = *(const float4*)(wrow + 4);
            #pragma unroll
            for (int rr = 0; rr < 8; rr++) {
                float xk = ((const float*)&xv[rr])[kk];
                acc[rr][0] = fmaf(xk, w0.x, acc[rr][0]);
                acc[rr][1] = fmaf(xk, w0.y, acc[rr][1]);
                acc[rr][2] = fmaf(xk, w0.z, acc[rr][2]);
                acc[rr][3] = fmaf(xk, w0.w, acc[rr][3]);
                acc[rr][4] = fmaf(xk, w1.x, acc[rr][4]);
                acc[rr][5] = fmaf(xk, w1.y, acc[rr][5]);
                acc[rr][6] = fmaf(xk, w1.z, acc[rr][6]);
                acc[rr][7] = fmaf(xk, w1.w, acc[rr][7]);
            }
        }
    }

    #pragma unroll
    for (int rr = 0; rr < 8; rr++) {
        int r = rbase + 32 * rr;
        if (r < n) {
            float dv = g_dinv[r];
            __half2 p0 = __floats2half2_rn(acc[rr][0] * dv, acc[rr][1] * dv);
            __half2 p1 = __floats2half2_rn(acc[rr][2] * dv, acc[rr][3] * dv);
            __half2 p2 = __floats2half2_rn(acc[rr][4] * dv, acc[rr][5] * dv);
            __half2 p3 = __floats2half2_rn(acc[rr][6] * dv, acc[rr][7] * dv);
            uint4 st;
            st.x = *(unsigned*)&p0; st.y = *(unsigned*)&p1;
            st.z = *(unsigned*)&p2; st.w = *(unsigned*)&p3;
            ((uint4*)(Yh + (size_t)r * 64))[cg] = st;
        }
    }
}

// ---------------- aggregation: 8 lanes/node, 8 feats (16B fp16) per lane ---
// out[i] = dinv[i] * ( H'[i] + sum_e w_e * H'[src_e] ) + bias   (fp32 accum)
// 8-wide clamped main loop: indices clamp to end-1, padded weights are zero,
// so every iteration issues 8 independent LDG.128 gathers (no remainder).
template <bool STATS, bool CLEAN>
__global__ void __launch_bounds__(256) k_agg(const __half* __restrict__ H,
                                             const float* __restrict__ bias,
                                             float* __restrict__ out, int n) {
    int tid = threadIdx.x;
    int sub = tid >> 3;         // 0..31 node slot
    int l8  = tid & 7;          // feature group (8 halves = 16B)
    int i   = blockIdx.x * 32 + sub;

    float acc[8];
    #pragma unroll
    for (int k = 0; k < 8; k++) acc[k] = 0.0f;

    if (i < n) {
        {   // self term (weight 1 in the dinv-scaled domain)
            uint4 u = ((const uint4*)(H + (size_t)i * 64))[l8];
            float2 f0 = __half22float2(*(const __half2*)&u.x);
            float2 f1 = __half22float2(*(const __half2*)&u.y);
            float2 f2 = __half22float2(*(const __half2*)&u.z);
            float2 f3 = __half22float2(*(const __half2*)&u.w);
            acc[0] = f0.x; acc[1] = f0.y; acc[2] = f1.x; acc[3] = f1.y;
            acc[4] = f2.x; acc[5] = f2.y; acc[6] = f3.x; acc[7] = f3.y;
        }

        int e   = g_rowptr[i];
        int end = g_rowptr[i + 1];

        for (int base = e; base < end; base += 8) {
            unsigned long long p[8];
            float wv[8];
            #pragma unroll
            for (int j = 0; j < 8; j++) {
                int idx = base + j < end ? base + j : end - 1;
                p[j] = g_edge[idx];
                wv[j] = (base + j < end)
                        ? __uint_as_float((unsigned)(p[j] >> 32)) : 0.0f;
            }
            uint4 u[8];
            #pragma unroll
            for (int j = 0; j < 8; j++)
                u[j] = ((const uint4*)(H + (size_t)(unsigned)p[j] * 64))[l8];
            #pragma unroll
            for (int j = 0; j < 8; j++) {
                #pragma unroll
                for (int q = 0; q < 4; q++) {
                    unsigned lo = (&u[j].x)[q];
                    float2 f = __half22float2(*(const __half2*)&lo);
                    acc[2*q]   = fmaf(wv[j], f.x, acc[2*q]);
                    acc[2*q+1] = fmaf(wv[j], f.y, acc[2*q+1]);
                }
            }
        }

        float dv = g_dinv[i];
        const float4* B4 = (const float4*)bias;
        float4 b0 = B4[l8 * 2], b1 = B4[l8 * 2 + 1];
        float4 o0 = make_float4(fmaf(dv, acc[0], b0.x), fmaf(dv, acc[1], b0.y),
                                fmaf(dv, acc[2], b0.z), fmaf(dv, acc[3], b0.w));
        float4 o1 = make_float4(fmaf(dv, acc[4], b1.x), fmaf(dv, acc[5], b1.y),
                                fmaf(dv, acc[6], b1.z), fmaf(dv, acc[7], b1.w));
        float4* O4 = (float4*)(out + (size_t)i * 64);
        O4[l8 * 2] = o0; O4[l8 * 2 + 1] = o1;
        acc[0]=o0.x; acc[1]=o0.y; acc[2]=o0.z; acc[3]=o0.w;
        acc[4]=o1.x; acc[5]=o1.y; acc[6]=o1.z; acc[7]=o1.w;
    } else {
        #pragma unroll
        for (int k = 0; k < 8; k++) acc[k] = 0.0f;
    }

    if (STATS) {
        __shared__ __align__(16) float sacc[32][68];
        float4* row = (float4*)&sacc[sub][l8 * 8];
        row[0] = make_float4(acc[0], acc[1], acc[2], acc[3]);
        row[1] = make_float4(acc[4], acc[5], acc[6], acc[7]);
        __syncthreads();
        if (tid < 64) {
            float s = 0.f, q = 0.f;
            #pragma unroll
            for (int k = 0; k < 32; k++) {
                float v = sacc[k][tid];
                s += v;
                q += v * v;
            }
            atomicAdd(&g_bnsum[tid], s);
            atomicAdd(&g_bnsq[tid],  q);
        }
    }

    if (CLEAN) {
        // restore all-zero invariant (everything else fully rewritten per call)
        int g = blockIdx.x * 256 + tid;
        if (g < n) g_degcnt[g] = 0ULL;
        if (g < DF) { g_bnsum[g] = 0.0f; g_bnsq[g] = 0.0f; }
    }
}

// ---------------------------------------------------------------------------
// Fork resources: created once on the first (uncaptured correctness) call so
// nothing is created during graph capture; the event fork/join becomes
// parallel edges in the captured graph. GPU work is identical every call.
static cudaStream_t g_s2  = nullptr;
static cudaEvent_t  g_ev1 = nullptr;
static cudaEvent_t  g_ev2 = nullptr;

extern "C" void kernel_launch(void* const* d_in, const int* in_sizes, int n_in,
                              void* d_out, int out_size) {
    const float* x     = (const float*)d_in[0];
    const int*   ei    = (const int*)d_in[1];
    const float* ew    = (const float*)d_in[2];
    const float* W1    = (const float*)d_in[3];
    const float* b1    = (const float*)d_in[4];
    const float* gamma = (const float*)d_in[5];
    const float* beta  = (const float*)d_in[6];
    const float* W2    = (const float*)d_in[7];
    const float* b2    = (const float*)d_in[8];

    int N = in_sizes[0] / DF;
    int E = in_sizes[2];
    if (N > NN || E > EE) return;

    if (!g_s2) {
        cudaStreamCreateWithFlags(&g_s2, cudaStreamNonBlocking);
        cudaEventCreateWithFlags(&g_ev1, cudaEventDisableTiming);
        cudaEventCreateWithFlags(&g_ev2, cudaEventDisableTiming);
    }

    __half *p_h1, *p_h2;
    float *p_ha;
    cudaGetSymbolAddress((void**)&p_h1, g_h1);
    cudaGetSymbolAddress((void**)&p_ha, g_ha);
    cudaGetSymbolAddress((void**)&p_h2, g_h2);

    int nb = (N + 1023) / 1024;
    float invn = 1.0f / (float)N;

    // ---- CSR build chain (stream 0) ----
    if ((E & 3) == 0)
        k_edge_deg<<<(E / 4 + 255) / 256, 256>>>(ei, ew, E);
    else
        k_edge_deg_s<<<(E + 255) / 256, 256>>>(ei, ew, E);
    k_scan_a<<<nb, 1024>>>(N);

    // ---- fork: GEMM1 (needs only dinv) runs concurrent with scan_c+fill ----
    cudaEventRecord(g_ev1, 0);
    cudaStreamWaitEvent(g_s2, g_ev1, 0);
    k_gemm<false><<<(N + 127) / 128, 256, 0, g_s2>>>(x, W1, p_h1, N,
                                                     nullptr, nullptr, 0.f);
    cudaEventRecord(g_ev2, g_s2);

    k_scan_c<<<nb, 1024>>>(N, nb);
    if ((E & 1) == 0)
        k_fill<<<(E / 2 + 255) / 256, 256>>>(ei, ew, E);
    else
        k_fill_s<<<(E + 255) / 256, 256>>>(ei, ew, E);

    cudaStreamWaitEvent(0, g_ev2, 0);   // join before agg1

    // ---- serial tail (data-dependent) ----
    k_agg<true, false><<<(N + 31) / 32, 256>>>(p_h1, b1, p_ha, N);
    k_gemm<true><<<(N + 127) / 128, 256>>>(p_ha, W2, p_h2, N, gamma, beta, invn);
    k_agg<false, true><<<(N + 31) / 32, 256>>>(p_h2, b2, (float*)d_out, N);
}